// round 15
// baseline (speedup 1.0000x reference)
#include <cuda_runtime.h>
#include <cuda_bf16.h>
#include <math.h>
#include <stdint.h>

#define HW 96
#define P  (96*96)          // 9216
#define BB 4
#define CC 64
#define CAT 448
#define HEAD 256

typedef __nv_bfloat16 bf16;

// ---------------- cp.async helpers -----------------------------------------------
__device__ __forceinline__ unsigned smem_u32(const void* p) {
    return (unsigned)__cvta_generic_to_shared(p);
}
__device__ __forceinline__ void cp16(unsigned dst, const void* src) {
    asm volatile("cp.async.cg.shared.global [%0], [%1], 16;"
                 :: "r"(dst), "l"(src));
}
__device__ __forceinline__ void cp16z(unsigned dst, const void* src, int sz) {
    asm volatile("cp.async.cg.shared.global [%0], [%1], 16, %2;"
                 :: "r"(dst), "l"(src), "r"(sz));
}
__device__ __forceinline__ void cp_commit() {
    asm volatile("cp.async.commit_group;");
}
template<int N>
__device__ __forceinline__ void cp_wait() {
    asm volatile("cp.async.wait_group %0;" :: "n"(N));
}

// ---------------- bf16 split helpers ---------------------------------------------
__device__ __forceinline__ void split_bf16(float v, bf16 &h, bf16 &l) {
    h = __float2bfloat16_rn(v);
    l = __float2bfloat16_rn(v - __bfloat162float(h));
}

// ---------------- mma.sync m16n8k16 bf16 + ldmatrix ------------------------------
__device__ __forceinline__ void mma16(float d[4], const unsigned a[4], const unsigned b[2]) {
    asm volatile(
        "mma.sync.aligned.m16n8k16.row.col.f32.bf16.bf16.f32 "
        "{%0,%1,%2,%3}, {%4,%5,%6,%7}, {%8,%9}, {%0,%1,%2,%3};"
        : "+f"(d[0]), "+f"(d[1]), "+f"(d[2]), "+f"(d[3])
        : "r"(a[0]), "r"(a[1]), "r"(a[2]), "r"(a[3]), "r"(b[0]), "r"(b[1]));
}
__device__ __forceinline__ void ldsm4(unsigned &r0, unsigned &r1, unsigned &r2, unsigned &r3,
                                      unsigned addr) {
    asm volatile("ldmatrix.sync.aligned.m8n8.x4.shared.b16 {%0,%1,%2,%3}, [%4];"
                 : "=r"(r0), "=r"(r1), "=r"(r2), "=r"(r3) : "r"(addr));
}

// ---------------- scratch (device globals) ---------------------------------------
__device__ float g_featT[28*P*CC];          // NHWC fp32 (for DCN bilinear)
__device__ bf16  g_fTh  [28*P*CC];          // NHWC bf16 hi
__device__ bf16  g_fTl  [28*P*CC];          // NHWC bf16 lo
__device__ bf16  g_colsh[4L*P*4032];        // dcn gather hi [b][p][gk*64+c]
__device__ bf16  g_colsl[4L*P*4032];
__device__ float g_wh1 [28*HEAD*P];
__device__ float g_hm1 [BB*HEAD*P];
__device__ float g_id1 [BB*HEAD*P];
__device__ float g_off [BB*189*P];
__device__ float g_d   [BB*HEAD*P];
__device__ bf16  g_wh_h[HEAD*576],  g_wh_l[HEAD*576];
__device__ bf16  g_hm_h[HEAD*576],  g_hm_l[HEAD*576];
__device__ bf16  g_id_h[HEAD*4032], g_id_l[HEAD*4032];
__device__ bf16  g_of_h[189*4032],  g_of_l[189*4032];
__device__ bf16  g_wt_h[HEAD*4032], g_wt_l[HEAD*4032];

// ---------------- transpose + bf16 split: feat[n][c][p] -> featT/fTh/fTl ---------
__global__ __launch_bounds__(256) void transpose_k(const float* __restrict__ f,
                                                   float* __restrict__ fT,
                                                   bf16* __restrict__ fTh,
                                                   bf16* __restrict__ fTl) {
    __shared__ float sm[64][65];
    int n = blockIdx.y, p0 = blockIdx.x * 64;
    const float* src = f + (long)n*CC*P;
    for (int i = threadIdx.x; i < 4096; i += 256) {
        int c = i >> 6, x = i & 63;
        sm[x][c] = src[(long)c*P + p0 + x];
    }
    __syncthreads();
    long base = ((long)n*P + p0)*CC;
    for (int i = threadIdx.x; i < 4096; i += 256) {
        int x = i >> 6, c = i & 63;
        float v = sm[x][c];
        long o = base + (long)x*CC + c;
        fT[o] = v;
        bf16 h, l; split_bf16(v, h, l);
        fTh[o] = h; fTl[o] = l;
    }
}

// ---------------- weight reorders (fp32 -> bf16 hi/lo) ---------------------------
// tap-mode: w[oc][c][tap] -> wA[oc][tap*C+c]
__global__ __launch_bounds__(256) void reorder_w_tap_k(const float* __restrict__ w,
                                                       bf16* __restrict__ wh,
                                                       bf16* __restrict__ wl,
                                                       int C, int Cout) {
    int idx = blockIdx.x * 256 + threadIdx.x;
    int total = Cout * C * 9;
    if (idx >= total) return;
    int oc = idx / (C*9);
    int rr = idx % (C*9);
    int tap = rr / C, c = rr % C;
    float v = w[((long)oc*C + c)*9 + tap];
    bf16 h, l; split_bf16(v, h, l);
    wh[idx] = h; wl[idx] = l;
}

// cat-mode: w[oc][kimg*64+c][tap] -> wA[oc][(tap*7+kimg)*64+c]
__global__ __launch_bounds__(256) void reorder_w_cat_k(const float* __restrict__ w,
                                                       bf16* __restrict__ wh,
                                                       bf16* __restrict__ wl,
                                                       int Cout) {
    int idx = blockIdx.x * 256 + threadIdx.x;
    int total = Cout * 4032;
    if (idx >= total) return;
    int oc = idx / 4032;
    int rr = idx % 4032;
    int c  = rr & 63;
    int gi = rr >> 6;
    int tap = gi / 7, kimg = gi % 7;
    float v = w[((long)oc*CAT + kimg*64 + c)*9 + tap];
    bf16 h, l; split_bf16(v, h, l);
    wh[idx] = h; wl[idx] = l;
}

// dcn: -> wt[oc][(g*9+kk)*64+c]
__global__ __launch_bounds__(256) void reorder_dcn_w_k(const float* __restrict__ dcn_w,
                                                       bf16* __restrict__ wh,
                                                       bf16* __restrict__ wl) {
    int idx = blockIdx.x * 256 + threadIdx.x;   // 256*4032 exact
    int oc = idx / 4032;
    int k  = idx % 4032;
    int g  = k / 576;
    int r  = k % 576;
    int kk = r / 64;
    int c  = r % 64;
    float v = dcn_w[((long)oc*CAT + g*64 + c)*9 + kk];
    bf16 h, l; split_bf16(v, h, l);
    wh[idx] = h; wl[idx] = l;
}

// ---------------- DCN bilinear gather (fp32 math) -> bf16 hi/lo cols -------------
__global__ __launch_bounds__(256) void dcn_cols_k(const float* __restrict__ fT,
                                                  const float* __restrict__ off,
                                                  bf16* __restrict__ colsH,
                                                  bf16* __restrict__ colsL) {
    int p  = blockIdx.x * 256 + threadIdx.x;
    int gk = blockIdx.y;
    int b  = blockIdx.z;
    int yy = p / HW, xx = p % HW;
    const float* ob = off + (long)b*189*P + p;
    float oy = ob[gk*P];
    float ox = ob[(63+gk)*P];
    float m  = ob[(126+gk)*P];
    m = 1.f / (1.f + expf(-m));
    int kk = gk % 9;
    float sy = (float)(yy - 1 + kk/3) + oy;
    float sx = (float)(xx - 1 + kk%3) + ox;
    float y0f = floorf(sy), x0f = floorf(sx);
    float wy = sy - y0f, wx = sx - x0f;
    int y0 = (int)y0f, x0 = (int)x0f;
    int y1 = y0 + 1, x1 = x0 + 1;
    bool vy0 = (y0>=0)&&(y0<HW), vy1 = (y1>=0)&&(y1<HW);
    bool vx0 = (x0>=0)&&(x0<HW), vx1 = (x1>=0)&&(x1<HW);
    int cy0 = min(max(y0,0),HW-1), cy1 = min(max(y1,0),HW-1);
    int cx0 = min(max(x0,0),HW-1), cx1 = min(max(x1,0),HW-1);
    float w00 = (vy0&&vx0) ? (1.f-wy)*(1.f-wx)*m : 0.f;
    float w01 = (vy0&&vx1) ? (1.f-wy)*wx*m       : 0.f;
    float w10 = (vy1&&vx0) ? wy*(1.f-wx)*m       : 0.f;
    float w11 = (vy1&&vx1) ? wy*wx*m             : 0.f;
    int g = gk / 9;
    const float* xb = fT + (long)(g*BB + b)*P*CC;
    const float* r00 = xb + (long)(cy0*HW+cx0)*CC;
    const float* r01 = xb + (long)(cy0*HW+cx1)*CC;
    const float* r10 = xb + (long)(cy1*HW+cx0)*CC;
    const float* r11 = xb + (long)(cy1*HW+cx1)*CC;
    long cbo = ((long)b*P + p)*4032 + gk*64;
#pragma unroll 4
    for (int c4 = 0; c4 < 16; c4++) {
        float4 a = *(const float4*)(r00 + c4*4);
        float4 bq= *(const float4*)(r01 + c4*4);
        float4 cq= *(const float4*)(r10 + c4*4);
        float4 dq= *(const float4*)(r11 + c4*4);
        float4 r;
        r.x = w00*a.x + w01*bq.x + w10*cq.x + w11*dq.x;
        r.y = w00*a.y + w01*bq.y + w10*cq.y + w11*dq.y;
        r.z = w00*a.z + w01*bq.z + w10*cq.z + w11*dq.z;
        r.w = w00*a.w + w01*bq.w + w10*cq.w + w11*dq.w;
        bf16 hx,lx,hy,ly,hz,lz,hw,lw;
        split_bf16(r.x,hx,lx); split_bf16(r.y,hy,ly);
        split_bf16(r.z,hz,lz); split_bf16(r.w,hw,lw);
        __nv_bfloat162 h01; h01.x = hx; h01.y = hy;
        __nv_bfloat162 h23; h23.x = hz; h23.y = hw;
        __nv_bfloat162 l01; l01.x = lx; l01.y = ly;
        __nv_bfloat162 l23; l23.x = lz; l23.y = lw;
        *(__nv_bfloat162*)(colsH + cbo + c4*4    ) = h01;
        *(__nv_bfloat162*)(colsH + cbo + c4*4 + 2) = h23;
        *(__nv_bfloat162*)(colsL + cbo + c4*4    ) = l01;
        *(__nv_bfloat162*)(colsL + cbo + c4*4 + 2) = l23;
    }
}

// ---------------- generic bf16 tensor-core GEMM (3-term split) -------------------
// out[z][oc][p] = sum_k A[oc][k] * B[z][p][k]
// mode 0: B explicit bf16 [p][K] at Bh/Bl + z*zStride
// mode 1: B implicit im2col of NHWC fTh/fTl (C=64), gi=tap (K=576)
// mode 2: B implicit im2col of cat (7 images), gi=tap*7+kimg (K=4032)
#define PADB 40
#define SA_BUF (256*PADB)           // bf16 elements per A buffer
#define SB_BUF (64*PADB)
#define OFF_AH 0
#define OFF_AL (2*SA_BUF*2)
#define OFF_BH (4*SA_BUF*2)
#define OFF_BL (4*SA_BUF*2 + 2*SB_BUF*2)
#define GM_SMEM (4*SA_BUF*2 + 4*SB_BUF*2)   // 102400 bytes

__global__ __launch_bounds__(256) void gemm_tc_k(
    const bf16* __restrict__ Ah, const bf16* __restrict__ Al,
    const bf16* __restrict__ Bh, const bf16* __restrict__ Bl,
    long zStride, long kStride, int mode,
    long oStride, int K, int Mtot,
    const float* __restrict__ bias,
    const float* __restrict__ gamma, const float* __restrict__ beta,
    const float* __restrict__ mean, const float* __restrict__ var,
    int bn, int relu, float* __restrict__ out)
{
    extern __shared__ __align__(16) char gsm[];
    bf16* sAh = (bf16*)(gsm + OFF_AH);
    bf16* sAl = (bf16*)(gsm + OFF_AL);
    bf16* sBh = (bf16*)(gsm + OFF_BH);
    bf16* sBl = (bf16*)(gsm + OFF_BL);
    int tid = threadIdx.x, wid = tid >> 5, lane = tid & 31;
    int g = lane >> 2, t = lane & 3;
    int warpM = wid >> 1, warpN = wid & 1;
    int pBase = blockIdx.x * 64;
    int z = blockIdx.z;
    const bf16* Bzh = Bh + (long)z*zStride;
    const bf16* Bzl = Bl + (long)z*zStride;

    // ldmatrix per-lane offsets (elements): lanes 0-7 rows+0 k+0, 8-15 rows+8 k+0,
    // 16-23 rows+0 k+8, 24-31 rows+8 k+8  == ((lane&15) rows, (lane>>4)*8 k)
    int lmA = ((warpM*64 + (lane & 15))*PADB + ((lane >> 4) << 3)) * 2;  // bytes
    int lmB = ((warpN*32 + (lane & 15))*PADB + ((lane >> 4) << 3)) * 2;

    float acc[4][4][4];
#pragma unroll
    for (int mt=0;mt<4;mt++)
#pragma unroll
        for (int nt=0;nt<4;nt++)
#pragma unroll
            for (int i=0;i<4;i++) acc[mt][nt][i] = 0.f;

    auto stage = [&](int k0, int buf) {
        unsigned sah = smem_u32(sAh + buf*SA_BUF);
        unsigned sal = smem_u32(sAl + buf*SA_BUF);
        for (int i = tid; i < 1024; i += 256) {       // 256 rows x 4 x 8bf16
            int m = i >> 2, j = i & 3;
            int mm = min(m, Mtot-1);
            long so = (long)mm*K + k0 + j*8;
            unsigned d = (m*PADB + j*8)*2;
            cp16(sah + d, Ah + so);
            cp16(sal + d, Al + so);
        }
        unsigned sbh = smem_u32(sBh + buf*SB_BUF);
        unsigned sbl = smem_u32(sBl + buf*SB_BUF);
        if (mode == 0) {
            for (int i = tid; i < 256; i += 256) {    // 64 rows x 4 x 8bf16
                int r = i >> 2, j = i & 3;
                long so = (long)(pBase + r)*K + k0 + j*8;
                unsigned d = (r*PADB + j*8)*2;
                cp16(sbh + d, Bzh + so);
                cp16(sbl + d, Bzl + so);
            }
        } else {
            int cIdx = k0 >> 5;
            int gi = cIdx >> 1, half = cIdx & 1;
            int tap, kimg;
            if (mode == 1) { tap = gi; kimg = 0; }
            else           { tap = gi / 7; kimg = gi - tap*7; }
            int dy = tap/3 - 1, dx = tap - (tap/3)*3 - 1;
            const bf16* sh = Bzh + (long)kimg*kStride;
            const bf16* sl = Bzl + (long)kimg*kStride;
            for (int i = tid; i < 256; i += 256) {
                int r = i >> 2, j = i & 3;
                int p = pBase + r;
                int y = p / HW, x = p - y*HW;
                int yy = y + dy, xx = x + dx;
                bool ok = ((unsigned)yy < HW) && ((unsigned)xx < HW);
                long so = ok ? ((long)(yy*HW + xx))*CC + half*32 + j*8 : 0;
                int sz = ok ? 16 : 0;
                unsigned d = (r*PADB + j*8)*2;
                cp16z(sbh + d, sh + so, sz);
                cp16z(sbl + d, sl + so, sz);
            }
        }
    };

    int NCH = K / 32;
    stage(0, 0);
    cp_commit();
    for (int c = 0; c < NCH; c++) {
        int buf = c & 1;
        if (c + 1 < NCH) { stage((c+1)*32, buf^1); cp_commit(); cp_wait<1>(); }
        else             { cp_wait<0>(); }
        __syncthreads();
        unsigned baseAh = smem_u32(sAh + buf*SA_BUF) + lmA;
        unsigned baseAl = smem_u32(sAl + buf*SA_BUF) + lmA;
        unsigned baseBh = smem_u32(sBh + buf*SB_BUF) + lmB;
        unsigned baseBl = smem_u32(sBl + buf*SB_BUF) + lmB;
#pragma unroll
        for (int ks = 0; ks < 2; ks++) {
            int kbB = ks*16*2;   // byte offset along k
            unsigned bh[4][2], bl[4][2];
#pragma unroll
            for (int pr = 0; pr < 2; pr++) {
                unsigned off = pr*16*PADB*2 + kbB;
                // x4 tiles: t0 = rows+0..7 k0-7 -> b0 of nt=2pr; t1 = rows 8-15 -> b0 of nt=2pr+1;
                //           t2 = rows 0-7 k8-15 -> b1 of nt=2pr; t3 -> b1 of nt=2pr+1
                ldsm4(bh[2*pr][0], bh[2*pr+1][0], bh[2*pr][1], bh[2*pr+1][1], baseBh + off);
                ldsm4(bl[2*pr][0], bl[2*pr+1][0], bl[2*pr][1], bl[2*pr+1][1], baseBl + off);
            }
#pragma unroll
            for (int mt = 0; mt < 4; mt++) {
                unsigned off = mt*16*PADB*2 + kbB;
                unsigned ah[4], al[4];
                ldsm4(ah[0], ah[1], ah[2], ah[3], baseAh + off);
                ldsm4(al[0], al[1], al[2], al[3], baseAl + off);
#pragma unroll
                for (int nt = 0; nt < 4; nt++) mma16(acc[mt][nt], ah, bh[nt]);
#pragma unroll
                for (int nt = 0; nt < 4; nt++) mma16(acc[mt][nt], al, bh[nt]);
#pragma unroll
                for (int nt = 0; nt < 4; nt++) mma16(acc[mt][nt], ah, bl[nt]);
            }
        }
        __syncthreads();
    }

    // epilogue
#pragma unroll
    for (int mt = 0; mt < 4; mt++) {
        int ocL = warpM*64 + mt*16 + g;
        int ocH = ocL + 8;
        float scL = 1.f, bbL = 0.f, btL = 0.f;
        float scH = 1.f, bbH = 0.f, btH = 0.f;
        if (ocL < Mtot) {
            bbL = bias[ocL];
            if (bn) { scL = gamma[ocL]*rsqrtf(var[ocL]+1e-5f); bbL -= mean[ocL]; btL = beta[ocL]; }
        }
        if (ocH < Mtot) {
            bbH = bias[ocH];
            if (bn) { scH = gamma[ocH]*rsqrtf(var[ocH]+1e-5f); bbH -= mean[ocH]; btH = beta[ocH]; }
        }
        float* oL = out + (long)z*oStride + (long)ocL*P + pBase + warpN*32;
        float* oH = out + (long)z*oStride + (long)ocH*P + pBase + warpN*32;
#pragma unroll
        for (int nt = 0; nt < 4; nt++) {
            int pc = nt*8 + 2*t;
            float2 vL, vH;
            vL.x = (acc[mt][nt][0] + bbL)*scL + btL;
            vL.y = (acc[mt][nt][1] + bbL)*scL + btL;
            vH.x = (acc[mt][nt][2] + bbH)*scH + btH;
            vH.y = (acc[mt][nt][3] + bbH)*scH + btH;
            if (relu) {
                vL.x = fmaxf(vL.x, 0.f); vL.y = fmaxf(vL.y, 0.f);
                vH.x = fmaxf(vH.x, 0.f); vH.y = fmaxf(vH.y, 0.f);
            }
            if (ocL < Mtot) *(float2*)(oL + pc) = vL;
            if (ocH < Mtot) *(float2*)(oH + pc) = vH;
        }
    }
}

// ---------------- conv1x1 (Cin=256) ----------------------------------------------
template<int OCT>
__global__ __launch_bounds__(256) void conv1x1_k(const float* __restrict__ in,
                                                 const float* __restrict__ w,
                                                 const float* __restrict__ bias,
                                                 float* __restrict__ out,
                                                 int Cout, int owh_mode) {
    const int Cin = 256;
    __shared__ float s_w[OCT*Cin];
    int tid = threadIdx.x;
    int n = blockIdx.y;
    int ocBase = blockIdx.z * OCT;
    for (int idx = tid; idx < OCT*Cin; idx += 256)
        s_w[idx] = w[(long)(ocBase + idx / Cin)*Cin + (idx % Cin)];
    __syncthreads();
    int px = blockIdx.x * 512 + tid * 2;
    const float* inp = in + (long)n*Cin*P + px;
    float2 acc[OCT];
#pragma unroll
    for (int o=0;o<OCT;o++) acc[o] = make_float2(0.f, 0.f);
#pragma unroll 4
    for (int ic = 0; ic < Cin; ic++) {
        float2 v = *(const float2*)(inp + (long)ic*P);
#pragma unroll
        for (int o=0;o<OCT;o++) {
            float wv = s_w[o*Cin + ic];
            acc[o].x += wv * v.x;
            acc[o].y += wv * v.y;
        }
    }
#pragma unroll
    for (int o=0;o<OCT;o++) {
        int oc = ocBase + o;
        float bv = bias[oc];
        float2 r = make_float2(acc[o].x + bv, acc[o].y + bv);
        long oidx;
        if (owh_mode) { int b = n & 3, k = n >> 2; oidx = (long)(b*14 + k*2 + oc)*P + px; }
        else          { oidx = ((long)n*Cout + oc)*P + px; }
        *(float2*)(out + oidx) = r;
    }
}

// -------------------------------- launch -----------------------------------------
extern "C" void kernel_launch(void* const* d_in, const int* in_sizes, int n_in,
                              void* d_out, int out_size) {
    const float* feat    = (const float*)d_in[0];
    const float* hm_w1   = (const float*)d_in[1];
    const float* hm_b1   = (const float*)d_in[2];
    const float* hm_w2   = (const float*)d_in[3];
    const float* hm_b2   = (const float*)d_in[4];
    const float* wh_w1   = (const float*)d_in[5];
    const float* wh_b1   = (const float*)d_in[6];
    const float* wh_w2   = (const float*)d_in[7];
    const float* wh_b2   = (const float*)d_in[8];
    const float* id_w1   = (const float*)d_in[9];
    const float* id_b1   = (const float*)d_in[10];
    const float* id_w2   = (const float*)d_in[11];
    const float* id_b2   = (const float*)d_in[12];
    const float* off_w   = (const float*)d_in[13];
    const float* off_b   = (const float*)d_in[14];
    const float* dcn_w   = (const float*)d_in[15];
    const float* dcn_b   = (const float*)d_in[16];
    const float* bn_g    = (const float*)d_in[17];
    const float* bn_b    = (const float*)d_in[18];
    const float* bn_m    = (const float*)d_in[19];
    const float* bn_v    = (const float*)d_in[20];
    const float* bz_w    = (const float*)d_in[21];
    const float* bz_b    = (const float*)d_in[22];
    float* out = (float*)d_out;

    void *p_featT, *p_fTh, *p_fTl, *p_colsh, *p_colsl;
    void *p_wh1, *p_hm1, *p_id1, *p_off, *p_d;
    void *p_wh_h, *p_wh_l, *p_hm_h, *p_hm_l, *p_id_h, *p_id_l, *p_of_h, *p_of_l, *p_wt_h, *p_wt_l;
    cudaGetSymbolAddress(&p_featT, g_featT);
    cudaGetSymbolAddress(&p_fTh,   g_fTh);
    cudaGetSymbolAddress(&p_fTl,   g_fTl);
    cudaGetSymbolAddress(&p_colsh, g_colsh);
    cudaGetSymbolAddress(&p_colsl, g_colsl);
    cudaGetSymbolAddress(&p_wh1,   g_wh1);
    cudaGetSymbolAddress(&p_hm1,   g_hm1);
    cudaGetSymbolAddress(&p_id1,   g_id1);
    cudaGetSymbolAddress(&p_off,   g_off);
    cudaGetSymbolAddress(&p_d,     g_d);
    cudaGetSymbolAddress(&p_wh_h,  g_wh_h);
    cudaGetSymbolAddress(&p_wh_l,  g_wh_l);
    cudaGetSymbolAddress(&p_hm_h,  g_hm_h);
    cudaGetSymbolAddress(&p_hm_l,  g_hm_l);
    cudaGetSymbolAddress(&p_id_h,  g_id_h);
    cudaGetSymbolAddress(&p_id_l,  g_id_l);
    cudaGetSymbolAddress(&p_of_h,  g_of_h);
    cudaGetSymbolAddress(&p_of_l,  g_of_l);
    cudaGetSymbolAddress(&p_wt_h,  g_wt_h);
    cudaGetSymbolAddress(&p_wt_l,  g_wt_l);
    float* featT = (float*)p_featT;
    bf16*  fTh   = (bf16*)p_fTh;
    bf16*  fTl   = (bf16*)p_fTl;
    bf16*  colsh = (bf16*)p_colsh;
    bf16*  colsl = (bf16*)p_colsl;
    float* wh1   = (float*)p_wh1;
    float* hm1   = (float*)p_hm1;
    float* id1   = (float*)p_id1;
    float* offv  = (float*)p_off;
    float* dv    = (float*)p_d;

    cudaFuncSetAttribute(gemm_tc_k,
                         cudaFuncAttributeMaxDynamicSharedMemorySize, GM_SMEM);

    const long osH = (long)HEAD*P;
    const long zImg = (long)P*CC;       // per-image stride (elements)
    const long kImg = (long)BB*P*CC;    // per-kimg stride within cat

    // 1 transpose, 2 reorder wh, 3 reorder hm, 4 wh GEMM (profile target)
    transpose_k<<<dim3(144, 28), 256>>>(feat, featT, fTh, fTl);
    reorder_w_tap_k<<<(HEAD*576+255)/256, 256>>>(wh_w1, (bf16*)p_wh_h, (bf16*)p_wh_l, CC, HEAD);
    reorder_w_tap_k<<<(HEAD*576+255)/256, 256>>>(hm_w1, (bf16*)p_hm_h, (bf16*)p_hm_l, CC, HEAD);
    gemm_tc_k<<<dim3(144, 1, 28), 256, GM_SMEM>>>((bf16*)p_wh_h, (bf16*)p_wh_l, fTh, fTl,
        zImg, 0, 1, osH, 576, HEAD, wh_b1, bn_g, bn_b, bn_m, bn_v, 0, 1, wh1);
    // hm: images 12..15
    gemm_tc_k<<<dim3(144, 1, 4), 256, GM_SMEM>>>((bf16*)p_hm_h, (bf16*)p_hm_l, fTh + 12*zImg, fTl + 12*zImg,
        zImg, 0, 1, osH, 576, HEAD, hm_b1, bn_g, bn_b, bn_m, bn_v, 0, 1, hm1);

    reorder_w_cat_k<<<(HEAD*4032+255)/256, 256>>>(id_w1, (bf16*)p_id_h, (bf16*)p_id_l, HEAD);
    reorder_w_cat_k<<<(189*4032+255)/256, 256>>>(off_w, (bf16*)p_of_h, (bf16*)p_of_l, 189);
    reorder_dcn_w_k<<<(4032*HEAD)/256, 256>>>(dcn_w, (bf16*)p_wt_h, (bf16*)p_wt_l);

    // id / off GEMMs: cat-mode implicit im2col
    gemm_tc_k<<<dim3(144, 1, BB), 256, GM_SMEM>>>((bf16*)p_id_h, (bf16*)p_id_l, fTh, fTl,
        zImg, kImg, 2, osH, 4032, HEAD, id_b1, bn_g, bn_b, bn_m, bn_v, 0, 1, id1);
    gemm_tc_k<<<dim3(144, 1, BB), 256, GM_SMEM>>>((bf16*)p_of_h, (bf16*)p_of_l, fTh, fTl,
        zImg, kImg, 2, (long)189*P, 4032, 189, off_b, bn_g, bn_b, bn_m, bn_v, 0, 0, offv);

    // DCN gather + GEMM (explicit B, BN + relu fused)
    dcn_cols_k<<<dim3(P/256, 63, BB), 256>>>(featT, offv, colsh, colsl);
    gemm_tc_k<<<dim3(144, 1, BB), 256, GM_SMEM>>>((bf16*)p_wt_h, (bf16*)p_wt_l, colsh, colsl,
        (long)P*4032, 0, 0, osH, 4032, HEAD, dcn_b, bn_g, bn_b, bn_m, bn_v, 1, 1, dv);

    // 1x1 heads -> output regions (hm, bz, idout, owh)
    float* out_hm  = out;
    float* out_bz  = out + (long)BB*24*P;
    float* out_id  = out_bz + (long)BB*16*P;
    float* out_owh = out_id + (long)BB*128*P;

    conv1x1_k<24><<<dim3(18, BB, 1), 256>>>(hm1, hm_w2, hm_b2, out_hm, 24, 0);
    conv1x1_k<16><<<dim3(18, BB, 1), 256>>>(dv,  bz_w,  bz_b,  out_bz, 16, 0);
    conv1x1_k<32><<<dim3(18, BB, 4), 256>>>(id1, id_w2, id_b2, out_id, 128, 0);
    conv1x1_k<2> <<<dim3(18, 28, 1), 256>>>(wh1, wh_w2, wh_b2, out_owh, 2, 1);
}

// round 17
// speedup vs baseline: 1.7507x; 1.7507x over previous
#include <cuda_runtime.h>
#include <cuda_fp16.h>
#include <math.h>
#include <stdint.h>

#define HW 96
#define P  (96*96)          // 9216
#define BB 4
#define CC 64
#define CAT 448
#define HEAD 256

// ---------------- cp.async helpers -----------------------------------------------
__device__ __forceinline__ unsigned smem_u32(const void* p) {
    return (unsigned)__cvta_generic_to_shared(p);
}
__device__ __forceinline__ void cp16(unsigned dst, const void* src) {
    asm volatile("cp.async.cg.shared.global [%0], [%1], 16;"
                 :: "r"(dst), "l"(src));
}
__device__ __forceinline__ void cp16z(unsigned dst, const void* src, int sz) {
    asm volatile("cp.async.cg.shared.global [%0], [%1], 16, %2;"
                 :: "r"(dst), "l"(src), "r"(sz));
}
__device__ __forceinline__ void cp_commit() {
    asm volatile("cp.async.commit_group;");
}
template<int N>
__device__ __forceinline__ void cp_wait() {
    asm volatile("cp.async.wait_group %0;" :: "n"(N));
}

// ---------------- mma.sync m16n8k16 fp16 -----------------------------------------
__device__ __forceinline__ void mma16(float d[4], const unsigned a[4], const unsigned b[2]) {
    asm volatile(
        "mma.sync.aligned.m16n8k16.row.col.f32.f16.f16.f32 "
        "{%0,%1,%2,%3}, {%4,%5,%6,%7}, {%8,%9}, {%0,%1,%2,%3};"
        : "+f"(d[0]), "+f"(d[1]), "+f"(d[2]), "+f"(d[3])
        : "r"(a[0]), "r"(a[1]), "r"(a[2]), "r"(a[3]), "r"(b[0]), "r"(b[1]));
}

// ---------------- scratch (device globals) ---------------------------------------
__device__ float  g_featT[28*P*CC];          // NHWC fp32 (for DCN bilinear)
__device__ __half g_fTh  [28*P*CC];          // NHWC fp16
__device__ __half g_cols [4L*P*4032];        // dcn gather [b][p][gk*64+c]
__device__ float  g_wh1 [28*HEAD*P];
__device__ float  g_hm1 [BB*HEAD*P];
__device__ float  g_id1 [BB*HEAD*P];
__device__ float  g_off [BB*189*P];
__device__ float  g_d   [BB*HEAD*P];
__device__ __half g_wh_h[HEAD*576];
__device__ __half g_hm_h[HEAD*576];
__device__ __half g_id_h[HEAD*4032];
__device__ __half g_of_h[189*4032];
__device__ __half g_wt_h[HEAD*4032];

// ---------------- transpose + fp16: feat[n][c][p] -> featT / fTh -----------------
__global__ __launch_bounds__(256) void transpose_k(const float* __restrict__ f,
                                                   float* __restrict__ fT,
                                                   __half* __restrict__ fTh) {
    __shared__ float sm[64][65];
    int n = blockIdx.y, p0 = blockIdx.x * 64;
    const float* src = f + (long)n*CC*P;
    for (int i = threadIdx.x; i < 4096; i += 256) {
        int c = i >> 6, x = i & 63;
        sm[x][c] = src[(long)c*P + p0 + x];
    }
    __syncthreads();
    long base = ((long)n*P + p0)*CC;
    for (int i = threadIdx.x; i < 4096; i += 256) {
        int x = i >> 6, c = i & 63;
        float v = sm[x][c];
        long o = base + (long)x*CC + c;
        fT[o] = v;
        fTh[o] = __float2half_rn(v);
    }
}

// ---------------- weight reorders (fp32 -> fp16) ---------------------------------
// tap-mode: w[oc][c][tap] -> wA[oc][tap*C+c]
__global__ __launch_bounds__(256) void reorder_w_tap_k(const float* __restrict__ w,
                                                       __half* __restrict__ wh,
                                                       int C, int Cout) {
    int idx = blockIdx.x * 256 + threadIdx.x;
    int total = Cout * C * 9;
    if (idx >= total) return;
    int oc = idx / (C*9);
    int rr = idx % (C*9);
    int tap = rr / C, c = rr % C;
    wh[idx] = __float2half_rn(w[((long)oc*C + c)*9 + tap]);
}

// cat-mode: w[oc][kimg*64+c][tap] -> wA[oc][(tap*7+kimg)*64+c]
__global__ __launch_bounds__(256) void reorder_w_cat_k(const float* __restrict__ w,
                                                       __half* __restrict__ wh,
                                                       int Cout) {
    int idx = blockIdx.x * 256 + threadIdx.x;
    int total = Cout * 4032;
    if (idx >= total) return;
    int oc = idx / 4032;
    int rr = idx % 4032;
    int c  = rr & 63;
    int gi = rr >> 6;
    int tap = gi / 7, kimg = gi % 7;
    wh[idx] = __float2half_rn(w[((long)oc*CAT + kimg*64 + c)*9 + tap]);
}

// dcn: -> wt[oc][(g*9+kk)*64+c]
__global__ __launch_bounds__(256) void reorder_dcn_w_k(const float* __restrict__ dcn_w,
                                                       __half* __restrict__ wh) {
    int idx = blockIdx.x * 256 + threadIdx.x;   // 256*4032 exact
    int oc = idx / 4032;
    int k  = idx % 4032;
    int g  = k / 576;
    int r  = k % 576;
    int kk = r / 64;
    int c  = r % 64;
    wh[idx] = __float2half_rn(dcn_w[((long)oc*CAT + g*64 + c)*9 + kk]);
}

// ---------------- DCN bilinear gather (fp32 math) -> fp16 cols -------------------
__global__ __launch_bounds__(256) void dcn_cols_k(const float* __restrict__ fT,
                                                  const float* __restrict__ off,
                                                  __half* __restrict__ colsH) {
    int p  = blockIdx.x * 256 + threadIdx.x;
    int gk = blockIdx.y;
    int b  = blockIdx.z;
    int yy = p / HW, xx = p % HW;
    const float* ob = off + (long)b*189*P + p;
    float oy = ob[gk*P];
    float ox = ob[(63+gk)*P];
    float m  = ob[(126+gk)*P];
    m = 1.f / (1.f + expf(-m));
    int kk = gk % 9;
    float sy = (float)(yy - 1 + kk/3) + oy;
    float sx = (float)(xx - 1 + kk%3) + ox;
    float y0f = floorf(sy), x0f = floorf(sx);
    float wy = sy - y0f, wx = sx - x0f;
    int y0 = (int)y0f, x0 = (int)x0f;
    int y1 = y0 + 1, x1 = x0 + 1;
    bool vy0 = (y0>=0)&&(y0<HW), vy1 = (y1>=0)&&(y1<HW);
    bool vx0 = (x0>=0)&&(x0<HW), vx1 = (x1>=0)&&(x1<HW);
    int cy0 = min(max(y0,0),HW-1), cy1 = min(max(y1,0),HW-1);
    int cx0 = min(max(x0,0),HW-1), cx1 = min(max(x1,0),HW-1);
    float w00 = (vy0&&vx0) ? (1.f-wy)*(1.f-wx)*m : 0.f;
    float w01 = (vy0&&vx1) ? (1.f-wy)*wx*m       : 0.f;
    float w10 = (vy1&&vx0) ? wy*(1.f-wx)*m       : 0.f;
    float w11 = (vy1&&vx1) ? wy*wx*m             : 0.f;
    int g = gk / 9;
    const float* xb = fT + (long)(g*BB + b)*P*CC;
    const float* r00 = xb + (long)(cy0*HW+cx0)*CC;
    const float* r01 = xb + (long)(cy0*HW+cx1)*CC;
    const float* r10 = xb + (long)(cy1*HW+cx0)*CC;
    const float* r11 = xb + (long)(cy1*HW+cx1)*CC;
    long cbo = ((long)b*P + p)*4032 + gk*64;
#pragma unroll 4
    for (int c4 = 0; c4 < 16; c4++) {
        float4 a = *(const float4*)(r00 + c4*4);
        float4 bq= *(const float4*)(r01 + c4*4);
        float4 cq= *(const float4*)(r10 + c4*4);
        float4 dq= *(const float4*)(r11 + c4*4);
        float4 r;
        r.x = w00*a.x + w01*bq.x + w10*cq.x + w11*dq.x;
        r.y = w00*a.y + w01*bq.y + w10*cq.y + w11*dq.y;
        r.z = w00*a.z + w01*bq.z + w10*cq.z + w11*dq.z;
        r.w = w00*a.w + w01*bq.w + w10*cq.w + w11*dq.w;
        __half2 h01 = __floats2half2_rn(r.x, r.y);
        __half2 h23 = __floats2half2_rn(r.z, r.w);
        *(__half2*)(colsH + cbo + c4*4    ) = h01;
        *(__half2*)(colsH + cbo + c4*4 + 2) = h23;
    }
}

// ---------------- generic fp16 tensor-core GEMM ----------------------------------
// out[z][oc][p] = sum_k A[oc][k] * B[z][p][k]
// mode 0: B explicit fp16 [p][K] at Bh + z*zStride
// mode 1: B implicit im2col of NHWC fTh (C=64), gi=tap (K=576)
// mode 2: B implicit im2col of cat (7 images), gi=tap*7+kimg (K=4032)
#define PADB 40
#define SA_BUF (256*PADB)           // fp16 elements per A buffer
#define SB_BUF (64*PADB)
#define OFF_A 0
#define OFF_B (2*SA_BUF*2)
#define GM_SMEM ((2*SA_BUF + 2*SB_BUF)*2)   // 51200 bytes

__global__ __launch_bounds__(256) void gemm_tc_k(
    const __half* __restrict__ Ah,
    const __half* __restrict__ Bh,
    long zStride, long kStride, int mode,
    long oStride, int K, int Mtot,
    const float* __restrict__ bias,
    const float* __restrict__ gamma, const float* __restrict__ beta,
    const float* __restrict__ mean, const float* __restrict__ var,
    int bn, int relu, float* __restrict__ out)
{
    extern __shared__ __align__(16) char gsm[];
    __half* sA = (__half*)(gsm + OFF_A);
    __half* sB = (__half*)(gsm + OFF_B);
    int tid = threadIdx.x, wid = tid >> 5, lane = tid & 31;
    int g = lane >> 2, t = lane & 3;
    int warpM = wid >> 1, warpN = wid & 1;
    int pBase = blockIdx.x * 64;
    int z = blockIdx.z;
    const __half* Bz = Bh + (long)z*zStride;

    float acc[4][4][4];
#pragma unroll
    for (int mt=0;mt<4;mt++)
#pragma unroll
        for (int nt=0;nt<4;nt++)
#pragma unroll
            for (int i=0;i<4;i++) acc[mt][nt][i] = 0.f;

    auto stage = [&](int k0, int buf) {
        unsigned sa = smem_u32(sA + buf*SA_BUF);
        for (int i = tid; i < 1024; i += 256) {       // 256 rows x 4 x 8fp16
            int m = i >> 2, j = i & 3;
            int mm = min(m, Mtot-1);
            long so = (long)mm*K + k0 + j*8;
            cp16(sa + (m*PADB + j*8)*2, Ah + so);
        }
        unsigned sbm = smem_u32(sB + buf*SB_BUF);
        if (mode == 0) {
            for (int i = tid; i < 256; i += 256) {    // 64 rows x 4 x 8fp16
                int r = i >> 2, j = i & 3;
                long so = (long)(pBase + r)*K + k0 + j*8;
                cp16(sbm + (r*PADB + j*8)*2, Bz + so);
            }
        } else {
            int cIdx = k0 >> 5;
            int gi = cIdx >> 1, half = cIdx & 1;
            int tap, kimg;
            if (mode == 1) { tap = gi; kimg = 0; }
            else           { tap = gi / 7; kimg = gi - tap*7; }
            int dy = tap/3 - 1, dx = tap - (tap/3)*3 - 1;
            const __half* sh = Bz + (long)kimg*kStride;
            for (int i = tid; i < 256; i += 256) {
                int r = i >> 2, j = i & 3;
                int p = pBase + r;
                int y = p / HW, x = p - y*HW;
                int yy = y + dy, xx = x + dx;
                bool ok = ((unsigned)yy < HW) && ((unsigned)xx < HW);
                long so = ok ? ((long)(yy*HW + xx))*CC + half*32 + j*8 : 0;
                cp16z(sbm + (r*PADB + j*8)*2, sh + so, ok ? 16 : 0);
            }
        }
    };

    int NCH = K / 32;
    stage(0, 0);
    cp_commit();
    for (int c = 0; c < NCH; c++) {
        int buf = c & 1;
        if (c + 1 < NCH) { stage((c+1)*32, buf^1); cp_commit(); cp_wait<1>(); }
        else             { cp_wait<0>(); }
        __syncthreads();
        const __half* Aw = sA + buf*SA_BUF + (warpM*64)*PADB;
        const __half* Bw = sB + buf*SB_BUF + (warpN*32)*PADB;
#pragma unroll
        for (int ks = 0; ks < 2; ks++) {
            int kb = ks*16;
            unsigned bfr[4][2];
#pragma unroll
            for (int nt = 0; nt < 4; nt++) {
                int ro = (nt*8 + g)*PADB + kb + 2*t;
                bfr[nt][0] = *(const unsigned*)(Bw + ro);
                bfr[nt][1] = *(const unsigned*)(Bw + ro + 8);
            }
#pragma unroll
            for (int mt = 0; mt < 4; mt++) {
                int r0 = (mt*16 + g)*PADB + kb + 2*t;
                int r1 = (mt*16 + g + 8)*PADB + kb + 2*t;
                unsigned afr[4];
                afr[0] = *(const unsigned*)(Aw + r0);
                afr[1] = *(const unsigned*)(Aw + r1);
                afr[2] = *(const unsigned*)(Aw + r0 + 8);
                afr[3] = *(const unsigned*)(Aw + r1 + 8);
#pragma unroll
                for (int nt = 0; nt < 4; nt++) mma16(acc[mt][nt], afr, bfr[nt]);
            }
        }
        __syncthreads();
    }

    // epilogue
#pragma unroll
    for (int mt = 0; mt < 4; mt++) {
        int ocL = warpM*64 + mt*16 + g;
        int ocH = ocL + 8;
        float scL = 1.f, bbL = 0.f, btL = 0.f;
        float scH = 1.f, bbH = 0.f, btH = 0.f;
        if (ocL < Mtot) {
            bbL = bias[ocL];
            if (bn) { scL = gamma[ocL]*rsqrtf(var[ocL]+1e-5f); bbL -= mean[ocL]; btL = beta[ocL]; }
        }
        if (ocH < Mtot) {
            bbH = bias[ocH];
            if (bn) { scH = gamma[ocH]*rsqrtf(var[ocH]+1e-5f); bbH -= mean[ocH]; btH = beta[ocH]; }
        }
        float* oL = out + (long)z*oStride + (long)ocL*P + pBase + warpN*32;
        float* oH = out + (long)z*oStride + (long)ocH*P + pBase + warpN*32;
#pragma unroll
        for (int nt = 0; nt < 4; nt++) {
            int pc = nt*8 + 2*t;
            float2 vL, vH;
            vL.x = (acc[mt][nt][0] + bbL)*scL + btL;
            vL.y = (acc[mt][nt][1] + bbL)*scL + btL;
            vH.x = (acc[mt][nt][2] + bbH)*scH + btH;
            vH.y = (acc[mt][nt][3] + bbH)*scH + btH;
            if (relu) {
                vL.x = fmaxf(vL.x, 0.f); vL.y = fmaxf(vL.y, 0.f);
                vH.x = fmaxf(vH.x, 0.f); vH.y = fmaxf(vH.y, 0.f);
            }
            if (ocL < Mtot) *(float2*)(oL + pc) = vL;
            if (ocH < Mtot) *(float2*)(oH + pc) = vH;
        }
    }
}

// ---------------- conv1x1 (Cin=256) ----------------------------------------------
template<int OCT>
__global__ __launch_bounds__(256) void conv1x1_k(const float* __restrict__ in,
                                                 const float* __restrict__ w,
                                                 const float* __restrict__ bias,
                                                 float* __restrict__ out,
                                                 int Cout, int owh_mode) {
    const int Cin = 256;
    __shared__ float s_w[OCT*Cin];
    int tid = threadIdx.x;
    int n = blockIdx.y;
    int ocBase = blockIdx.z * OCT;
    for (int idx = tid; idx < OCT*Cin; idx += 256)
        s_w[idx] = w[(long)(ocBase + idx / Cin)*Cin + (idx % Cin)];
    __syncthreads();
    int px = blockIdx.x * 512 + tid * 2;
    const float* inp = in + (long)n*Cin*P + px;
    float2 acc[OCT];
#pragma unroll
    for (int o=0;o<OCT;o++) acc[o] = make_float2(0.f, 0.f);
#pragma unroll 4
    for (int ic = 0; ic < Cin; ic++) {
        float2 v = *(const float2*)(inp + (long)ic*P);
#pragma unroll
        for (int o=0;o<OCT;o++) {
            float wv = s_w[o*Cin + ic];
            acc[o].x += wv * v.x;
            acc[o].y += wv * v.y;
        }
    }
#pragma unroll
    for (int o=0;o<OCT;o++) {
        int oc = ocBase + o;
        float bv = bias[oc];
        float2 r = make_float2(acc[o].x + bv, acc[o].y + bv);
        long oidx;
        if (owh_mode) { int b = n & 3, k = n >> 2; oidx = (long)(b*14 + k*2 + oc)*P + px; }
        else          { oidx = ((long)n*Cout + oc)*P + px; }
        *(float2*)(out + oidx) = r;
    }
}

// -------------------------------- launch -----------------------------------------
extern "C" void kernel_launch(void* const* d_in, const int* in_sizes, int n_in,
                              void* d_out, int out_size) {
    const float* feat    = (const float*)d_in[0];
    const float* hm_w1   = (const float*)d_in[1];
    const float* hm_b1   = (const float*)d_in[2];
    const float* hm_w2   = (const float*)d_in[3];
    const float* hm_b2   = (const float*)d_in[4];
    const float* wh_w1   = (const float*)d_in[5];
    const float* wh_b1   = (const float*)d_in[6];
    const float* wh_w2   = (const float*)d_in[7];
    const float* wh_b2   = (const float*)d_in[8];
    const float* id_w1   = (const float*)d_in[9];
    const float* id_b1   = (const float*)d_in[10];
    const float* id_w2   = (const float*)d_in[11];
    const float* id_b2   = (const float*)d_in[12];
    const float* off_w   = (const float*)d_in[13];
    const float* off_b   = (const float*)d_in[14];
    const float* dcn_w   = (const float*)d_in[15];
    const float* dcn_b   = (const float*)d_in[16];
    const float* bn_g    = (const float*)d_in[17];
    const float* bn_b    = (const float*)d_in[18];
    const float* bn_m    = (const float*)d_in[19];
    const float* bn_v    = (const float*)d_in[20];
    const float* bz_w    = (const float*)d_in[21];
    const float* bz_b    = (const float*)d_in[22];
    float* out = (float*)d_out;

    void *p_featT, *p_fTh, *p_cols;
    void *p_wh1, *p_hm1, *p_id1, *p_off, *p_d;
    void *p_wh_h, *p_hm_h, *p_id_h, *p_of_h, *p_wt_h;
    cudaGetSymbolAddress(&p_featT, g_featT);
    cudaGetSymbolAddress(&p_fTh,   g_fTh);
    cudaGetSymbolAddress(&p_cols,  g_cols);
    cudaGetSymbolAddress(&p_wh1,   g_wh1);
    cudaGetSymbolAddress(&p_hm1,   g_hm1);
    cudaGetSymbolAddress(&p_id1,   g_id1);
    cudaGetSymbolAddress(&p_off,   g_off);
    cudaGetSymbolAddress(&p_d,     g_d);
    cudaGetSymbolAddress(&p_wh_h,  g_wh_h);
    cudaGetSymbolAddress(&p_hm_h,  g_hm_h);
    cudaGetSymbolAddress(&p_id_h,  g_id_h);
    cudaGetSymbolAddress(&p_of_h,  g_of_h);
    cudaGetSymbolAddress(&p_wt_h,  g_wt_h);
    float*  featT = (float*)p_featT;
    __half* fTh   = (__half*)p_fTh;
    __half* cols  = (__half*)p_cols;
    float* wh1   = (float*)p_wh1;
    float* hm1   = (float*)p_hm1;
    float* id1   = (float*)p_id1;
    float* offv  = (float*)p_off;
    float* dv    = (float*)p_d;

    cudaFuncSetAttribute(gemm_tc_k,
                         cudaFuncAttributeMaxDynamicSharedMemorySize, GM_SMEM);

    const long osH = (long)HEAD*P;
    const long zImg = (long)P*CC;       // per-image stride (elements)
    const long kImg = (long)BB*P*CC;    // per-kimg stride within cat

    // 1 transpose, 2 reorder wh, 3 reorder hm, 4 wh GEMM (profile target)
    transpose_k<<<dim3(144, 28), 256>>>(feat, featT, fTh);
    reorder_w_tap_k<<<(HEAD*576+255)/256, 256>>>(wh_w1, (__half*)p_wh_h, CC, HEAD);
    reorder_w_tap_k<<<(HEAD*576+255)/256, 256>>>(hm_w1, (__half*)p_hm_h, CC, HEAD);
    gemm_tc_k<<<dim3(144, 1, 28), 256, GM_SMEM>>>((__half*)p_wh_h, fTh,
        zImg, 0, 1, osH, 576, HEAD, wh_b1, bn_g, bn_b, bn_m, bn_v, 0, 1, wh1);
    // hm: images 12..15
    gemm_tc_k<<<dim3(144, 1, 4), 256, GM_SMEM>>>((__half*)p_hm_h, fTh + 12*zImg,
        zImg, 0, 1, osH, 576, HEAD, hm_b1, bn_g, bn_b, bn_m, bn_v, 0, 1, hm1);

    reorder_w_cat_k<<<(HEAD*4032+255)/256, 256>>>(id_w1, (__half*)p_id_h, HEAD);
    reorder_w_cat_k<<<(189*4032+255)/256, 256>>>(off_w, (__half*)p_of_h, 189);
    reorder_dcn_w_k<<<(4032*HEAD)/256, 256>>>(dcn_w, (__half*)p_wt_h);

    // id / off GEMMs: cat-mode implicit im2col
    gemm_tc_k<<<dim3(144, 1, BB), 256, GM_SMEM>>>((__half*)p_id_h, fTh,
        zImg, kImg, 2, osH, 4032, HEAD, id_b1, bn_g, bn_b, bn_m, bn_v, 0, 1, id1);
    gemm_tc_k<<<dim3(144, 1, BB), 256, GM_SMEM>>>((__half*)p_of_h, fTh,
        zImg, kImg, 2, (long)189*P, 4032, 189, off_b, bn_g, bn_b, bn_m, bn_v, 0, 0, offv);

    // DCN gather + GEMM (explicit B, BN + relu fused)
    dcn_cols_k<<<dim3(P/256, 63, BB), 256>>>(featT, offv, cols);
    gemm_tc_k<<<dim3(144, 1, BB), 256, GM_SMEM>>>((__half*)p_wt_h, cols,
        (long)P*4032, 0, 0, osH, 4032, HEAD, dcn_b, bn_g, bn_b, bn_m, bn_v, 1, 1, dv);

    // 1x1 heads -> output regions (hm, bz, idout, owh)
    float* out_hm  = out;
    float* out_bz  = out + (long)BB*24*P;
    float* out_id  = out_bz + (long)BB*16*P;
    float* out_owh = out_id + (long)BB*128*P;

    conv1x1_k<24><<<dim3(18, BB, 1), 256>>>(hm1, hm_w2, hm_b2, out_hm, 24, 0);
    conv1x1_k<16><<<dim3(18, BB, 1), 256>>>(dv,  bz_w,  bz_b,  out_bz, 16, 0);
    conv1x1_k<32><<<dim3(18, BB, 4), 256>>>(id1, id_w2, id_b2, out_id, 128, 0);
    conv1x1_k<2> <<<dim3(18, 28, 1), 256>>>(wh1, wh_w2, wh_b2, out_owh, 2, 1);
}